// round 1
// baseline (speedup 1.0000x reference)
#include <cuda_runtime.h>
#include <cuda_bf16.h>
#include <math.h>

// Problem constants
#define NTOK 2048   // S*B
#define DDIM 512
#define FDIM 2048
#define NEXP 8
#define TOPK 2

// Scratch (device globals; allocation-free per harness rules)
__device__ int   g_counts[NEXP];
__device__ int   g_lists[NEXP * NTOK];        // entry = token*2 + slot
__device__ float g_gatew[NTOK * 2];           // per (token, slot) routing weight
__device__ float g_h [NEXP * NTOK * FDIM];    // routed FFN1 activations (per expert list pos)
__device__ float g_hs[NTOK * FDIM];           // shared FFN1 activations

// ---------------------------------------------------------------------------
__global__ void zero_counts_kernel() {
    if (threadIdx.x < NEXP) g_counts[threadIdx.x] = 0;
}

// ---------------------------------------------------------------------------
// Gate: one warp per token. logits = x @ Wg + bg; top-2; softmax; build lists.
__global__ void gate_kernel(const float* __restrict__ x,
                            const float* __restrict__ Wg,
                            const float* __restrict__ bg) {
    int warp = threadIdx.x >> 5;
    int lane = threadIdx.x & 31;
    int t = blockIdx.x * 4 + warp;
    if (t >= NTOK) return;

    const float* xr = x + (size_t)t * DDIM;
    float acc[NEXP];
#pragma unroll
    for (int e = 0; e < NEXP; e++) acc[e] = 0.f;

#pragma unroll
    for (int i = 0; i < DDIM / 32; i++) {
        int d = i * 32 + lane;
        float xv = xr[d];
#pragma unroll
        for (int e = 0; e < NEXP; e++) acc[e] += xv * Wg[d * NEXP + e];
    }
#pragma unroll
    for (int e = 0; e < NEXP; e++) {
#pragma unroll
        for (int off = 16; off > 0; off >>= 1)
            acc[e] += __shfl_down_sync(0xFFFFFFFFu, acc[e], off);
    }
    if (lane == 0) {
        float lg[NEXP];
#pragma unroll
        for (int e = 0; e < NEXP; e++) lg[e] = acc[e] + bg[e];
        int i0 = 0;
#pragma unroll
        for (int e = 1; e < NEXP; e++) if (lg[e] > lg[i0]) i0 = e;
        int i1 = -1;
#pragma unroll
        for (int e = 0; e < NEXP; e++) {
            if (e == i0) continue;
            if (i1 < 0 || lg[e] > lg[i1]) i1 = e;
        }
        float l0 = lg[i0], l1 = lg[i1];
        float z  = expf(l1 - l0);     // <= 1
        float w0 = 1.f / (1.f + z);
        float w1 = z * w0;
        g_gatew[t * 2 + 0] = w0;
        g_gatew[t * 2 + 1] = w1;
        int p0 = atomicAdd(&g_counts[i0], 1);
        g_lists[i0 * NTOK + p0] = t * 2 + 0;
        int p1 = atomicAdd(&g_counts[i1], 1);
        g_lists[i1 * NTOK + p1] = t * 2 + 1;
    }
}

// ---------------------------------------------------------------------------
// Tiled SGEMM, 128x128 block tile, BK=8, 256 threads, 8x8 per thread.
// MODE 0: routed FFN1  h[e,pos,:] = relu(x[token(pos)] @ W1[e] + b1[e])
// MODE 1: routed FFN2  out[token] += w * (h[e,pos,:] @ W2[e] + b2[e])   (atomic)
// MODE 2: shared FFN1  hs = relu(x @ Ws1 + bs1)
// MODE 3: shared FFN2  out = 0.5*(hs @ Ws2 + bs2)                       (store)
#define BM 128
#define BN 128
#define BK 8

template <int MODE>
__global__ __launch_bounds__(256, 2)
void sgemm_kernel(const float* __restrict__ Ain,
                  const float* __restrict__ Bbase,
                  const float* __restrict__ biasbase,
                  float* __restrict__ outp,
                  int KK, int lda, int ldb) {
    const int e = (MODE <= 1) ? blockIdx.z : 0;
    int Mrows;
    const float* A;
    const float* B;
    const float* bv;
    if (MODE == 0) {
        Mrows = g_counts[e];
        A = Ain;                                    // x, lda=512
        B = Bbase + (size_t)e * KK * ldb;           // W1[e]
        bv = biasbase + (size_t)e * ldb;            // b1[e]
    } else if (MODE == 1) {
        Mrows = g_counts[e];
        A = g_h;                                    // lda=2048, src includes e offset
        B = Bbase + (size_t)e * KK * ldb;           // W2[e]
        bv = biasbase + (size_t)e * ldb;            // b2[e]
    } else if (MODE == 2) {
        Mrows = NTOK; A = Ain; B = Bbase; bv = biasbase;
    } else {
        Mrows = NTOK; A = g_hs; B = Bbase; bv = biasbase;
    }

    const int m0 = blockIdx.y * BM;
    if (m0 >= Mrows) return;
    const int n0 = blockIdx.x * BN;

    __shared__ float As[BK][BM];
    __shared__ float Bs[BK][BN];
    __shared__ int   rowsrc[BM];

    const int tid = threadIdx.x;

    // Row source indices for the A gather
    if (tid < BM) {
        int gr = m0 + tid;
        int src = -1;
        if (gr < Mrows) {
            if (MODE == 0)      src = g_lists[e * NTOK + gr] >> 1;   // token
            else if (MODE == 1) src = e * NTOK + gr;                  // h row
            else                src = gr;
        }
        rowsrc[tid] = src;
    }
    __syncthreads();

    float acc[8][8];
#pragma unroll
    for (int i = 0; i < 8; i++)
#pragma unroll
        for (int j = 0; j < 8; j++) acc[i][j] = 0.f;

    const int ar  = tid >> 1;            // A row in tile (0..127)
    const int ak4 = (tid & 1) * 4;       // A k offset (0 or 4)
    const int bk  = tid >> 5;            // B k row (0..7)
    const int bn4 = (tid & 31) * 4;      // B col offset (0..124)
    const int ty = tid >> 4;             // 0..15
    const int tx = tid & 15;             // 0..15

    for (int kt = 0; kt < KK; kt += BK) {
        // A tile (gathered rows) -> As[k][m]
        int src = rowsrc[ar];
        float4 av = make_float4(0.f, 0.f, 0.f, 0.f);
        if (src >= 0)
            av = *(const float4*)(A + (size_t)src * lda + kt + ak4);
        As[ak4 + 0][ar] = av.x;
        As[ak4 + 1][ar] = av.y;
        As[ak4 + 2][ar] = av.z;
        As[ak4 + 3][ar] = av.w;
        // B tile -> Bs[k][n]
        float4 bvv = *(const float4*)(B + (size_t)(kt + bk) * ldb + n0 + bn4);
        *(float4*)&Bs[bk][bn4] = bvv;
        __syncthreads();

#pragma unroll
        for (int k = 0; k < BK; k++) {
            float4 a0 = *(const float4*)&As[k][ty * 8];
            float4 a1 = *(const float4*)&As[k][ty * 8 + 4];
            float4 b0 = *(const float4*)&Bs[k][tx * 8];
            float4 b1 = *(const float4*)&Bs[k][tx * 8 + 4];
            float a[8] = {a0.x, a0.y, a0.z, a0.w, a1.x, a1.y, a1.z, a1.w};
            float b[8] = {b0.x, b0.y, b0.z, b0.w, b1.x, b1.y, b1.z, b1.w};
#pragma unroll
            for (int i = 0; i < 8; i++)
#pragma unroll
                for (int j = 0; j < 8; j++) acc[i][j] += a[i] * b[j];
        }
        __syncthreads();
    }

    // Epilogue
    float bb[8];
#pragma unroll
    for (int j = 0; j < 8; j++) bb[j] = bv[n0 + tx * 8 + j];

#pragma unroll
    for (int i = 0; i < 8; i++) {
        int m = m0 + ty * 8 + i;
        if (m >= Mrows) continue;
        if (MODE == 0) {
            float* C = g_h + (size_t)e * NTOK * FDIM + (size_t)m * FDIM + n0 + tx * 8;
#pragma unroll
            for (int j = 0; j < 8; j++) {
                float v = acc[i][j] + bb[j];
                C[j] = v > 0.f ? v : 0.f;
            }
        } else if (MODE == 2) {
            float* C = g_hs + (size_t)m * FDIM + n0 + tx * 8;
#pragma unroll
            for (int j = 0; j < 8; j++) {
                float v = acc[i][j] + bb[j];
                C[j] = v > 0.f ? v : 0.f;
            }
        } else if (MODE == 3) {
            float* C = outp + (size_t)m * DDIM + n0 + tx * 8;
#pragma unroll
            for (int j = 0; j < 8; j++) C[j] = 0.5f * (acc[i][j] + bb[j]);
        } else { // MODE == 1
            int entry = g_lists[e * NTOK + m];
            int t = entry >> 1;
            float w = g_gatew[entry];
            float* C = outp + (size_t)t * DDIM + n0 + tx * 8;
#pragma unroll
            for (int j = 0; j < 8; j++)
                atomicAdd(&C[j], w * (acc[i][j] + bb[j]));
        }
    }
}

// ---------------------------------------------------------------------------
extern "C" void kernel_launch(void* const* d_in, const int* in_sizes, int n_in,
                              void* d_out, int out_size) {
    const float* x   = (const float*)d_in[0];
    const float* Wg  = (const float*)d_in[1];
    const float* bg  = (const float*)d_in[2];
    const float* W1  = (const float*)d_in[3];
    const float* b1  = (const float*)d_in[4];
    const float* W2  = (const float*)d_in[5];
    const float* b2  = (const float*)d_in[6];
    const float* Ws1 = (const float*)d_in[7];
    const float* bs1 = (const float*)d_in[8];
    const float* Ws2 = (const float*)d_in[9];
    const float* bs2 = (const float*)d_in[10];
    float* out = (float*)d_out;

    zero_counts_kernel<<<1, 32>>>();
    gate_kernel<<<NTOK / 4, 128>>>(x, Wg, bg);

    // Routed FFN1: per expert, M<=2048, N=2048, K=512
    sgemm_kernel<0><<<dim3(FDIM / BN, NTOK / BM, NEXP), 256>>>(
        x, W1, b1, nullptr, DDIM, DDIM, FDIM);
    // Shared FFN1: M=2048, N=2048, K=512
    sgemm_kernel<2><<<dim3(FDIM / BN, NTOK / BM, 1), 256>>>(
        x, Ws1, bs1, nullptr, DDIM, DDIM, FDIM);
    // Shared FFN2 (writes base of out): M=2048, N=512, K=2048
    sgemm_kernel<3><<<dim3(DDIM / BN, NTOK / BM, 1), 256>>>(
        x, Ws2, bs2, out, FDIM, FDIM, DDIM);
    // Routed FFN2 (atomic adds on top): per expert, N=512, K=2048
    sgemm_kernel<1><<<dim3(DDIM / BN, NTOK / BM, NEXP), 256>>>(
        x, W2, b2, out, FDIM, FDIM, DDIM);
}

// round 2
// speedup vs baseline: 1.0459x; 1.0459x over previous
#include <cuda_runtime.h>
#include <cuda_bf16.h>
#include <math.h>

// Problem constants
#define NTOK 2048   // S*B
#define DDIM 512
#define FDIM 2048
#define NEXP 8
#define TOPK 2

// Scratch (device globals; allocation-free per harness rules)
__device__ int   g_counts[NEXP];
__device__ int   g_lists[NEXP * NTOK];        // entry = token*2 + slot
__device__ float g_gatew[NTOK * 2];           // per (token, slot) routing weight
__device__ float g_h [NEXP * NTOK * FDIM];    // routed FFN1 activations (per expert list pos)
__device__ float g_hs[NTOK * FDIM];           // shared FFN1 activations

// ---------------------------------------------------------------------------
__global__ void zero_counts_kernel() {
    if (threadIdx.x < NEXP) g_counts[threadIdx.x] = 0;
}

// ---------------------------------------------------------------------------
// Gate: one warp per token. logits = x @ Wg + bg; top-2; softmax; build lists.
__global__ void gate_kernel(const float* __restrict__ x,
                            const float* __restrict__ Wg,
                            const float* __restrict__ bg) {
    int warp = threadIdx.x >> 5;
    int lane = threadIdx.x & 31;
    int t = blockIdx.x * 4 + warp;
    if (t >= NTOK) return;

    const float* xr = x + (size_t)t * DDIM;
    float acc[NEXP];
#pragma unroll
    for (int e = 0; e < NEXP; e++) acc[e] = 0.f;

#pragma unroll
    for (int i = 0; i < DDIM / 32; i++) {
        int d = i * 32 + lane;
        float xv = xr[d];
#pragma unroll
        for (int e = 0; e < NEXP; e++) acc[e] += xv * Wg[d * NEXP + e];
    }
#pragma unroll
    for (int e = 0; e < NEXP; e++) {
#pragma unroll
        for (int off = 16; off > 0; off >>= 1)
            acc[e] += __shfl_down_sync(0xFFFFFFFFu, acc[e], off);
    }
    if (lane == 0) {
        float lg[NEXP];
#pragma unroll
        for (int e = 0; e < NEXP; e++) lg[e] = acc[e] + bg[e];
        int i0 = 0;
#pragma unroll
        for (int e = 1; e < NEXP; e++) if (lg[e] > lg[i0]) i0 = e;
        int i1 = -1;
#pragma unroll
        for (int e = 0; e < NEXP; e++) {
            if (e == i0) continue;
            if (i1 < 0 || lg[e] > lg[i1]) i1 = e;
        }
        float l0 = lg[i0], l1 = lg[i1];
        float z  = expf(l1 - l0);     // <= 1
        float w0 = 1.f / (1.f + z);
        float w1 = z * w0;
        g_gatew[t * 2 + 0] = w0;
        g_gatew[t * 2 + 1] = w1;
        int p0 = atomicAdd(&g_counts[i0], 1);
        g_lists[i0 * NTOK + p0] = t * 2 + 0;
        int p1 = atomicAdd(&g_counts[i1], 1);
        g_lists[i1 * NTOK + p1] = t * 2 + 1;
    }
}

// ---------------------------------------------------------------------------
// Tiled SGEMM, 128x128 block tile, BK=8, 256 threads, 8x8 per thread.
// MODE 0: routed FFN1  h[e,pos,:] = relu(x[token(pos)] @ W1[e] + b1[e])
// MODE 1: routed FFN2  out[token] += w * (h[e,pos,:] @ W2[e] + b2[e])   (atomic)
// MODE 2: shared FFN1  hs = relu(x @ Ws1 + bs1)
// MODE 3: shared FFN2  out = 0.5*(hs @ Ws2 + bs2)                       (store)
#define BM 128
#define BN 128
#define BK 8

template <int MODE>
__global__ __launch_bounds__(256, 2)
void sgemm_kernel(const float* __restrict__ Ain,
                  const float* __restrict__ Bbase,
                  const float* __restrict__ biasbase,
                  float* __restrict__ outp,
                  int KK, int lda, int ldb) {
    const int e = (MODE <= 1) ? blockIdx.z : 0;
    int Mrows;
    const float* A;
    const float* B;
    const float* bv;
    if (MODE == 0) {
        Mrows = g_counts[e];
        A = Ain;                                    // x, lda=512
        B = Bbase + (size_t)e * KK * ldb;           // W1[e]
        bv = biasbase + (size_t)e * ldb;            // b1[e]
    } else if (MODE == 1) {
        Mrows = g_counts[e];
        A = g_h;                                    // lda=2048, src includes e offset
        B = Bbase + (size_t)e * KK * ldb;           // W2[e]
        bv = biasbase + (size_t)e * ldb;            // b2[e]
    } else if (MODE == 2) {
        Mrows = NTOK; A = Ain; B = Bbase; bv = biasbase;
    } else {
        Mrows = NTOK; A = g_hs; B = Bbase; bv = biasbase;
    }

    const int m0 = blockIdx.y * BM;
    if (m0 >= Mrows) return;
    const int n0 = blockIdx.x * BN;

    __shared__ float As[BK][BM];
    __shared__ float Bs[BK][BN];
    __shared__ int   rowsrc[BM];

    const int tid = threadIdx.x;

    // Row source indices for the A gather
    if (tid < BM) {
        int gr = m0 + tid;
        int src = -1;
        if (gr < Mrows) {
            if (MODE == 0)      src = g_lists[e * NTOK + gr] >> 1;   // token
            else if (MODE == 1) src = e * NTOK + gr;                  // h row
            else                src = gr;
        }
        rowsrc[tid] = src;
    }
    __syncthreads();

    float acc[8][8];
#pragma unroll
    for (int i = 0; i < 8; i++)
#pragma unroll
        for (int j = 0; j < 8; j++) acc[i][j] = 0.f;

    const int ar  = tid >> 1;            // A row in tile (0..127)
    const int ak4 = (tid & 1) * 4;       // A k offset (0 or 4)
    const int bk  = tid >> 5;            // B k row (0..7)
    const int bn4 = (tid & 31) * 4;      // B col offset (0..124)
    const int ty = tid >> 4;             // 0..15
    const int tx = tid & 15;             // 0..15

    for (int kt = 0; kt < KK; kt += BK) {
        // A tile (gathered rows) -> As[k][m]
        int src = rowsrc[ar];
        float4 av = make_float4(0.f, 0.f, 0.f, 0.f);
        if (src >= 0)
            av = *(const float4*)(A + (size_t)src * lda + kt + ak4);
        As[ak4 + 0][ar] = av.x;
        As[ak4 + 1][ar] = av.y;
        As[ak4 + 2][ar] = av.z;
        As[ak4 + 3][ar] = av.w;
        // B tile -> Bs[k][n]
        float4 bvv = *(const float4*)(B + (size_t)(kt + bk) * ldb + n0 + bn4);
        *(float4*)&Bs[bk][bn4] = bvv;
        __syncthreads();

#pragma unroll
        for (int k = 0; k < BK; k++) {
            float4 a0 = *(const float4*)&As[k][ty * 8];
            float4 a1 = *(const float4*)&As[k][ty * 8 + 4];
            float4 b0 = *(const float4*)&Bs[k][tx * 8];
            float4 b1 = *(const float4*)&Bs[k][tx * 8 + 4];
            float a[8] = {a0.x, a0.y, a0.z, a0.w, a1.x, a1.y, a1.z, a1.w};
            float b[8] = {b0.x, b0.y, b0.z, b0.w, b1.x, b1.y, b1.z, b1.w};
#pragma unroll
            for (int i = 0; i < 8; i++)
#pragma unroll
                for (int j = 0; j < 8; j++) acc[i][j] += a[i] * b[j];
        }
        __syncthreads();
    }

    // Epilogue
    float bb[8];
#pragma unroll
    for (int j = 0; j < 8; j++) bb[j] = bv[n0 + tx * 8 + j];

#pragma unroll
    for (int i = 0; i < 8; i++) {
        int m = m0 + ty * 8 + i;
        if (m >= Mrows) continue;
        if (MODE == 0) {
            float* C = g_h + (size_t)e * NTOK * FDIM + (size_t)m * FDIM + n0 + tx * 8;
#pragma unroll
            for (int j = 0; j < 8; j++) {
                float v = acc[i][j] + bb[j];
                C[j] = v > 0.f ? v : 0.f;
            }
        } else if (MODE == 2) {
            float* C = g_hs + (size_t)m * FDIM + n0 + tx * 8;
#pragma unroll
            for (int j = 0; j < 8; j++) {
                float v = acc[i][j] + bb[j];
                C[j] = v > 0.f ? v : 0.f;
            }
        } else if (MODE == 3) {
            float* C = outp + (size_t)m * DDIM + n0 + tx * 8;
#pragma unroll
            for (int j = 0; j < 8; j++) C[j] = 0.5f * (acc[i][j] + bb[j]);
        } else { // MODE == 1
            int entry = g_lists[e * NTOK + m];
            int t = entry >> 1;
            float w = g_gatew[entry];
            float* C = outp + (size_t)t * DDIM + n0 + tx * 8;
#pragma unroll
            for (int j = 0; j < 8; j++)
                atomicAdd(&C[j], w * (acc[i][j] + bb[j]));
        }
    }
}

// ---------------------------------------------------------------------------
extern "C" void kernel_launch(void* const* d_in, const int* in_sizes, int n_in,
                              void* d_out, int out_size) {
    const float* x   = (const float*)d_in[0];
    const float* Wg  = (const float*)d_in[1];
    const float* bg  = (const float*)d_in[2];
    const float* W1  = (const float*)d_in[3];
    const float* b1  = (const float*)d_in[4];
    const float* W2  = (const float*)d_in[5];
    const float* b2  = (const float*)d_in[6];
    const float* Ws1 = (const float*)d_in[7];
    const float* bs1 = (const float*)d_in[8];
    const float* Ws2 = (const float*)d_in[9];
    const float* bs2 = (const float*)d_in[10];
    float* out = (float*)d_out;

    zero_counts_kernel<<<1, 32>>>();
    gate_kernel<<<NTOK / 4, 128>>>(x, Wg, bg);

    // Routed FFN1: per expert, M<=2048, N=2048, K=512
    sgemm_kernel<0><<<dim3(FDIM / BN, NTOK / BM, NEXP), 256>>>(
        x, W1, b1, nullptr, DDIM, DDIM, FDIM);
    // Shared FFN1: M=2048, N=2048, K=512
    sgemm_kernel<2><<<dim3(FDIM / BN, NTOK / BM, 1), 256>>>(
        x, Ws1, bs1, nullptr, DDIM, DDIM, FDIM);
    // Shared FFN2 (writes base of out): M=2048, N=512, K=2048
    sgemm_kernel<3><<<dim3(DDIM / BN, NTOK / BM, 1), 256>>>(
        x, Ws2, bs2, out, FDIM, FDIM, DDIM);
    // Routed FFN2 (atomic adds on top): per expert, N=512, K=2048
    sgemm_kernel<1><<<dim3(DDIM / BN, NTOK / BM, NEXP), 256>>>(
        x, W2, b2, out, FDIM, FDIM, DDIM);
}

// round 8
// speedup vs baseline: 1.2064x; 1.1534x over previous
#include <cuda_runtime.h>
#include <math.h>

#define NTOK 2048
#define DDIM 512
#define FDIM 2048
#define NEXP 8
#define BN 128
#define BK 16

__device__ int   g_counts[NEXP];
__device__ int   g_lists[NEXP * NTOK];
__device__ float g_gatew[NTOK * 2];
__device__ float g_h [(size_t)NEXP * NTOK * FDIM];
__device__ float g_hs[(size_t)NTOK * FDIM];

typedef unsigned long long ull;
__device__ __forceinline__ ull fma2(ull a, ull b, ull c) {
    ull d;
    asm("fma.rn.f32x2 %0, %1, %2, %3;" : "=l"(d) : "l"(a), "l"(b), "l"(c));
    return d;
}
__device__ __forceinline__ float2 unpack2(ull v) {
    float2 r;
    asm("mov.b64 {%0, %1}, %2;" : "=f"(r.x), "=f"(r.y) : "l"(v));
    return r;
}

// ---------------------------------------------------------------------------
__global__ void zero_counts_kernel() { if (threadIdx.x < NEXP) g_counts[threadIdx.x] = 0; }

__global__ void zero_out_kernel(float* __restrict__ out) {
    int i = blockIdx.x * 256 + threadIdx.x;
    ((float4*)out)[i] = make_float4(0.f, 0.f, 0.f, 0.f);
}

__global__ void gate_kernel(const float* __restrict__ x, const float* __restrict__ Wg,
                            const float* __restrict__ bg) {
    int warp = threadIdx.x >> 5, lane = threadIdx.x & 31;
    int t = blockIdx.x * 4 + warp;
    const float* xr = x + (size_t)t * DDIM;
    float acc[NEXP];
#pragma unroll
    for (int e = 0; e < NEXP; e++) acc[e] = 0.f;
#pragma unroll
    for (int i = 0; i < DDIM / 32; i++) {
        float xv = xr[i * 32 + lane];
#pragma unroll
        for (int e = 0; e < NEXP; e++) acc[e] += xv * Wg[(i * 32 + lane) * NEXP + e];
    }
#pragma unroll
    for (int e = 0; e < NEXP; e++)
#pragma unroll
        for (int off = 16; off > 0; off >>= 1)
            acc[e] += __shfl_down_sync(0xFFFFFFFFu, acc[e], off);
    if (lane == 0) {
        float lg[NEXP];
#pragma unroll
        for (int e = 0; e < NEXP; e++) lg[e] = acc[e] + bg[e];
        int i0 = 0;
#pragma unroll
        for (int e = 1; e < NEXP; e++) if (lg[e] > lg[i0]) i0 = e;
        int i1 = -1;
#pragma unroll
        for (int e = 0; e < NEXP; e++) {
            if (e == i0) continue;
            if (i1 < 0 || lg[e] > lg[i1]) i1 = e;
        }
        float z = expf(lg[i1] - lg[i0]);
        float w0 = 1.f / (1.f + z);
        g_gatew[t * 2 + 0] = w0;
        g_gatew[t * 2 + 1] = z * w0;
        int p0 = atomicAdd(&g_counts[i0], 1);
        g_lists[i0 * NTOK + p0] = t * 2 + 0;
        int p1 = atomicAdd(&g_counts[i1], 1);
        g_lists[i1 * NTOK + p1] = t * 2 + 1;
    }
}

// ---------------------------------------------------------------------------
// Fused FFMA2 GEMM. z = 0..7 routed expert, z = 8 shared expert.
// PHASE 1: C = relu(A @ B + bias) -> g_h (routed, A = x gathered) / g_hs (shared)
// PHASE 2: atomicAdd(out[row], w * (A @ B + bias)), w = gate weight / 0.5 (shared)
// A rows are K-major; B is (K, N) row-major, read directly (no transpose).
template <int PHASE, int BM_, int MI>
__global__ __launch_bounds__(256, 2)
void mm_kernel(const float* __restrict__ x,
               const float* __restrict__ W1, const float* __restrict__ b1,
               const float* __restrict__ W2, const float* __restrict__ b2,
               const float* __restrict__ Ws1, const float* __restrict__ bs1,
               const float* __restrict__ Ws2, const float* __restrict__ bs2,
               float* __restrict__ out) {
    constexpr int KK  = (PHASE == 1) ? DDIM : FDIM;   // reduction dim
    constexpr int NN  = (PHASE == 1) ? FDIM : DDIM;   // B row stride
    const int z = blockIdx.z;
    const bool se = (z == NEXP);
    const int Mrows = se ? NTOK : g_counts[z];
    const int m0 = blockIdx.y * BM_;
    if (m0 >= Mrows) return;
    const int n0 = blockIdx.x * BN;

    const float* A;
    const float* B;
    const float* bv;
    if (PHASE == 1) {
        A = x;
        B  = se ? Ws1 : W1 + (size_t)z * DDIM * FDIM;
        bv = se ? bs1 : b1 + (size_t)z * FDIM;
    } else {
        A  = se ? g_hs : g_h + (size_t)z * NTOK * FDIM;
        B  = se ? Ws2 : W2 + (size_t)z * FDIM * DDIM;
        bv = se ? bs2 : b2 + (size_t)z * DDIM;
    }

    __shared__ float As2[BK][2 * BM_];   // duplicated pairs (v, v)
    __shared__ float Bs[BK][BN];
    __shared__ int rowsrc[BM_];

    const int tid = threadIdx.x;
    if (tid < BM_) {
        int gr = m0 + tid, src = -1;
        if (gr < Mrows)
            src = (PHASE == 1 && !se) ? (g_lists[z * NTOK + gr] >> 1) : gr;
        rowsrc[tid] = src;
    }
    __syncthreads();

    // A loader: tpr threads per row, each covers 16/tpr k-floats
    constexpr int TPR = 256 / BM_;            // 2 (BM=128) or 4 (BM=64)
    constexpr int KPT = BK / TPR;             // 8 or 4
    const int lrow = tid / TPR;
    const int kofs = (tid % TPR) * KPT;
    const int asrc = rowsrc[lrow];
    const float* agp = A + (size_t)(asrc < 0 ? 0 : asrc) * KK;
    // B loader: rows kr, kr+8; 4 cols per thread
    const int kr = tid >> 5;
    const int c4 = (tid & 31) * 4;
    const float* bgp = B + n0 + c4;

    const int ty = tid >> 4;   // 0..15
    const int tx = tid & 15;   // 0..15

    ull acc[MI][4];
#pragma unroll
    for (int i = 0; i < MI; i++)
#pragma unroll
        for (int j = 0; j < 4; j++) acc[i][j] = 0ull;

    for (int kt = 0; kt < KK; kt += BK) {
        // A tile: duplicated store
#pragma unroll
        for (int qq = 0; qq < KPT / 4; qq++) {
            float4 av = make_float4(0.f, 0.f, 0.f, 0.f);
            if (asrc >= 0) av = *(const float4*)(agp + kt + kofs + qq * 4);
            *(float2*)&As2[kofs + qq * 4 + 0][2 * lrow] = make_float2(av.x, av.x);
            *(float2*)&As2[kofs + qq * 4 + 1][2 * lrow] = make_float2(av.y, av.y);
            *(float2*)&As2[kofs + qq * 4 + 2][2 * lrow] = make_float2(av.z, av.z);
            *(float2*)&As2[kofs + qq * 4 + 3][2 * lrow] = make_float2(av.w, av.w);
        }
        // B tile
        *(float4*)&Bs[kr][c4]     = *(const float4*)(bgp + (size_t)(kt + kr) * NN);
        *(float4*)&Bs[kr + 8][c4] = *(const float4*)(bgp + (size_t)(kt + kr + 8) * NN);
        __syncthreads();

#pragma unroll
        for (int k = 0; k < BK; k++) {
            const ull* ap = (const ull*)&As2[k][2 * ty * MI];
            const ull* bp = (const ull*)&Bs[k][tx * 8];
            ull b0 = bp[0], b1v = bp[1], b2v = bp[2], b3v = bp[3];
#pragma unroll
            for (int i = 0; i < MI; i++) {
                ull a = ap[i];
                acc[i][0] = fma2(a, b0,  acc[i][0]);
                acc[i][1] = fma2(a, b1v, acc[i][1]);
                acc[i][2] = fma2(a, b2v, acc[i][2]);
                acc[i][3] = fma2(a, b3v, acc[i][3]);
            }
        }
        __syncthreads();
    }

    // ---------------- epilogue ----------------
#pragma unroll
    for (int i = 0; i < MI; i++) {
        const int m = m0 + ty * MI + i;
        if (m >= Mrows) continue;
        if (PHASE == 1) {
            float* C = (se ? g_hs : g_h + (size_t)z * NTOK * FDIM) + (size_t)m * FDIM + n0 + tx * 8;
#pragma unroll
            for (int j = 0; j < 4; j++) {
                float2 v = unpack2(acc[i][j]);
                v.x = fmaxf(v.x + bv[n0 + tx * 8 + 2 * j],     0.f);
                v.y = fmaxf(v.y + bv[n0 + tx * 8 + 2 * j + 1], 0.f);
                *(float2*)(C + 2 * j) = v;
            }
        } else {
            float w;
            int row;
            if (se) { w = 0.5f; row = m; }
            else {
                int entry = g_lists[z * NTOK + m];
                w = g_gatew[entry];
                row = entry >> 1;
            }
            float* C = out + (size_t)row * DDIM + n0 + tx * 8;
#pragma unroll
            for (int j = 0; j < 4; j++) {
                float2 v = unpack2(acc[i][j]);
                atomicAdd(C + 2 * j,     w * (v.x + bv[n0 + tx * 8 + 2 * j]));
                atomicAdd(C + 2 * j + 1, w * (v.y + bv[n0 + tx * 8 + 2 * j + 1]));
            }
        }
    }
}

// ---------------------------------------------------------------------------
extern "C" void kernel_launch(void* const* d_in, const int* in_sizes, int n_in,
                              void* d_out, int out_size) {
    const float* x   = (const float*)d_in[0];
    const float* Wg  = (const float*)d_in[1];
    const float* bg  = (const float*)d_in[2];
    const float* W1  = (const float*)d_in[3];
    const float* b1  = (const float*)d_in[4];
    const float* W2  = (const float*)d_in[5];
    const float* b2  = (const float*)d_in[6];
    const float* Ws1 = (const float*)d_in[7];
    const float* bs1 = (const float*)d_in[8];
    const float* Ws2 = (const float*)d_in[9];
    const float* bs2 = (const float*)d_in[10];
    float* out = (float*)d_out;

    zero_counts_kernel<<<1, 32>>>();
    zero_out_kernel<<<(NTOK * DDIM / 4) / 256, 256>>>(out);
    gate_kernel<<<NTOK / 4, 128>>>(x, Wg, bg);

    // Phase 1: all FFN1 (8 routed + shared) in one launch. K=512, N=2048.
    mm_kernel<1, 128, 8><<<dim3(FDIM / BN, NTOK / 128, NEXP + 1), 256>>>(
        x, W1, b1, W2, b2, Ws1, bs1, Ws2, bs2, out);
    // Phase 2: all FFN2 in one launch, atomic accumulate. K=2048, N=512.
    mm_kernel<2, 64, 4><<<dim3(DDIM / BN, NTOK / 64, NEXP + 1), 256>>>(
        x, W1, b1, W2, b2, Ws1, bs1, Ws2, bs2, out);
}

// round 9
// speedup vs baseline: 1.5202x; 1.2601x over previous
#include <cuda_runtime.h>
#include <math.h>

#define NTOK 2048
#define DDIM 512
#define FDIM 2048
#define NEXP 8
#define BM 128
#define BN 128
#define BK 16
#define GS_A 20   // 8-row A-dup group: 16 data floats + 4 pad (80B stride)
#define GS_B 12   // 8-col B group: 8 data floats + 4 pad (48B stride)

__device__ int   g_counts[NEXP];
__device__ int   g_lists[NEXP * NTOK];
__device__ float g_gatew[NTOK * 2];
__device__ float g_h [(size_t)NEXP * NTOK * FDIM];
__device__ float g_hs[(size_t)NTOK * FDIM];

typedef unsigned long long ull;
__device__ __forceinline__ ull fma2(ull a, ull b, ull c) {
    ull d;
    asm("fma.rn.f32x2 %0, %1, %2, %3;" : "=l"(d) : "l"(a), "l"(b), "l"(c));
    return d;
}
__device__ __forceinline__ float2 unpack2(ull v) {
    float2 r;
    asm("mov.b64 {%0, %1}, %2;" : "=f"(r.x), "=f"(r.y) : "l"(v));
    return r;
}

// ---------------------------------------------------------------------------
__global__ void zero_counts_kernel() { if (threadIdx.x < NEXP) g_counts[threadIdx.x] = 0; }

__global__ void zero_out_kernel(float* __restrict__ out) {
    int i = blockIdx.x * 256 + threadIdx.x;
    ((float4*)out)[i] = make_float4(0.f, 0.f, 0.f, 0.f);
}

__global__ void gate_kernel(const float* __restrict__ x, const float* __restrict__ Wg,
                            const float* __restrict__ bg) {
    int warp = threadIdx.x >> 5, lane = threadIdx.x & 31;
    int t = blockIdx.x * 4 + warp;
    const float* xr = x + (size_t)t * DDIM;
    float acc[NEXP];
#pragma unroll
    for (int e = 0; e < NEXP; e++) acc[e] = 0.f;
#pragma unroll
    for (int i = 0; i < DDIM / 32; i++) {
        float xv = xr[i * 32 + lane];
#pragma unroll
        for (int e = 0; e < NEXP; e++) acc[e] += xv * Wg[(i * 32 + lane) * NEXP + e];
    }
#pragma unroll
    for (int e = 0; e < NEXP; e++)
#pragma unroll
        for (int off = 16; off > 0; off >>= 1)
            acc[e] += __shfl_down_sync(0xFFFFFFFFu, acc[e], off);
    if (lane == 0) {
        float lg[NEXP];
#pragma unroll
        for (int e = 0; e < NEXP; e++) lg[e] = acc[e] + bg[e];
        int i0 = 0;
#pragma unroll
        for (int e = 1; e < NEXP; e++) if (lg[e] > lg[i0]) i0 = e;
        int i1 = -1;
#pragma unroll
        for (int e = 0; e < NEXP; e++) {
            if (e == i0) continue;
            if (i1 < 0 || lg[e] > lg[i1]) i1 = e;
        }
        float z = expf(lg[i1] - lg[i0]);
        float w0 = 1.f / (1.f + z);
        g_gatew[t * 2 + 0] = w0;
        g_gatew[t * 2 + 1] = z * w0;
        int p0 = atomicAdd(&g_counts[i0], 1);
        g_lists[i0 * NTOK + p0] = t * 2 + 0;
        int p1 = atomicAdd(&g_counts[i1], 1);
        g_lists[i1 * NTOK + p1] = t * 2 + 1;
    }
}

// ---------------------------------------------------------------------------
// FFMA2 GEMM, warp tile 32Mx64N, lane tile 8Mx8N (acc pairs packed along N).
// z = 0..7 routed expert, z = 8 shared expert.
// PHASE 1: C = relu(A @ B + bias) -> g_h / g_hs
// PHASE 2: atomicAdd(out[row], w * (A @ B + bias))
template <int PHASE>
__global__ __launch_bounds__(256, 2)
void mm_kernel(const float* __restrict__ x,
               const float* __restrict__ W1, const float* __restrict__ b1,
               const float* __restrict__ W2, const float* __restrict__ b2,
               const float* __restrict__ Ws1, const float* __restrict__ bs1,
               const float* __restrict__ Ws2, const float* __restrict__ bs2,
               float* __restrict__ out) {
    constexpr int KK = (PHASE == 1) ? DDIM : FDIM;
    constexpr int NN = (PHASE == 1) ? FDIM : DDIM;
    const int z = blockIdx.z;
    const bool se = (z == NEXP);
    const int Mrows = se ? NTOK : g_counts[z];
    const int m0 = blockIdx.y * BM;
    if (m0 >= Mrows) return;
    const int n0 = blockIdx.x * BN;

    const float* A;
    const float* B;
    const float* bv;
    if (PHASE == 1) {
        A  = x;
        B  = se ? Ws1 : W1 + (size_t)z * DDIM * FDIM;
        bv = se ? bs1 : b1 + (size_t)z * FDIM;
    } else {
        A  = se ? g_hs : g_h + (size_t)z * NTOK * FDIM;
        B  = se ? Ws2 : W2 + (size_t)z * FDIM * DDIM;
        bv = se ? bs2 : b2 + (size_t)z * DDIM;
    }

    __shared__ float As2[BK][16 * GS_A];   // 16 groups of 8 dup rows
    __shared__ float Bs [BK][16 * GS_B];   // 16 groups of 8 cols
    __shared__ int rowsrc[BM];

    const int tid = threadIdx.x;
    if (tid < BM) {
        int gr = m0 + tid, src = -1;
        if (gr < Mrows)
            src = (PHASE == 1 && !se) ? (g_lists[z * NTOK + gr] >> 1) : gr;
        rowsrc[tid] = src;
    }
    __syncthreads();

    // Loaders
    const int lrow = tid >> 1;             // 0..127
    const int kofs = (tid & 1) * 8;        // 0 or 8
    const int a_st = (lrow >> 3) * GS_A + (lrow & 7) * 2;
    const int asrc = rowsrc[lrow];
    const float* agp = A + (size_t)(asrc < 0 ? 0 : asrc) * KK;
    const int kr = tid >> 5;               // 0..7
    const int c4 = (tid & 31) * 4;
    const int b_st = (c4 >> 3) * GS_B + (c4 & 7);
    const float* bgp = B + n0 + c4;

    // Fragment geometry
    const int lane = tid & 31;
    const int wid = tid >> 5;
    const int warpM = wid & 3;             // 0..3 -> 32-row slabs
    const int warpN = wid >> 2;            // 0..1 -> 64-col slabs
    const int am = lane >> 3;              // 0..3
    const int bn = lane & 7;               // 0..7
    const int a_off = (warpM * 4 + am) * GS_A;
    const int b_off = (warpN * 8 + bn) * GS_B;

    float4 pa0, pa1, pb0, pb1;
    auto loadregs = [&](int kt) {
        if (asrc >= 0) {
            pa0 = *(const float4*)(agp + kt + kofs);
            pa1 = *(const float4*)(agp + kt + kofs + 4);
        } else {
            pa0 = make_float4(0.f, 0.f, 0.f, 0.f);
            pa1 = pa0;
        }
        pb0 = *(const float4*)(bgp + (size_t)(kt + kr) * NN);
        pb1 = *(const float4*)(bgp + (size_t)(kt + kr + 8) * NN);
    };
    auto storesm = [&]() {
        *(float2*)&As2[kofs + 0][a_st] = make_float2(pa0.x, pa0.x);
        *(float2*)&As2[kofs + 1][a_st] = make_float2(pa0.y, pa0.y);
        *(float2*)&As2[kofs + 2][a_st] = make_float2(pa0.z, pa0.z);
        *(float2*)&As2[kofs + 3][a_st] = make_float2(pa0.w, pa0.w);
        *(float2*)&As2[kofs + 4][a_st] = make_float2(pa1.x, pa1.x);
        *(float2*)&As2[kofs + 5][a_st] = make_float2(pa1.y, pa1.y);
        *(float2*)&As2[kofs + 6][a_st] = make_float2(pa1.z, pa1.z);
        *(float2*)&As2[kofs + 7][a_st] = make_float2(pa1.w, pa1.w);
        *(float4*)&Bs[kr][b_st]     = pb0;
        *(float4*)&Bs[kr + 8][b_st] = pb1;
    };

    ull acc[8][4];
#pragma unroll
    for (int i = 0; i < 8; i++)
#pragma unroll
        for (int j = 0; j < 4; j++) acc[i][j] = 0ull;

    loadregs(0);
    storesm();

    for (int kt = 0; kt < KK; kt += BK) {
        __syncthreads();
        if (kt + BK < KK) loadregs(kt + BK);

#pragma unroll
        for (int k = 0; k < BK; k++) {
            const ull* ap = (const ull*)&As2[k][a_off];
            const ull* bp = (const ull*)&Bs[k][b_off];
            ull b0 = bp[0], b1v = bp[1], b2v = bp[2], b3v = bp[3];
#pragma unroll
            for (int i = 0; i < 8; i++) {
                ull a = ap[i];
                acc[i][0] = fma2(a, b0,  acc[i][0]);
                acc[i][1] = fma2(a, b1v, acc[i][1]);
                acc[i][2] = fma2(a, b2v, acc[i][2]);
                acc[i][3] = fma2(a, b3v, acc[i][3]);
            }
        }
        if (kt + BK < KK) {
            __syncthreads();
            storesm();
        }
    }

    // ---------------- epilogue ----------------
    const int cn = n0 + warpN * 64 + bn * 8;
    const float4 bb0 = *(const float4*)(bv + cn);
    const float4 bb1 = *(const float4*)(bv + cn + 4);
    const int mrow0 = m0 + warpM * 32 + am * 8;

#pragma unroll
    for (int i = 0; i < 8; i++) {
        const int m = mrow0 + i;
        if (m >= Mrows) continue;
        float2 v0 = unpack2(acc[i][0]);
        float2 v1 = unpack2(acc[i][1]);
        float2 v2 = unpack2(acc[i][2]);
        float2 v3 = unpack2(acc[i][3]);
        v0.x += bb0.x; v0.y += bb0.y;
        v1.x += bb0.z; v1.y += bb0.w;
        v2.x += bb1.x; v2.y += bb1.y;
        v3.x += bb1.z; v3.y += bb1.w;
        if (PHASE == 1) {
            float* C = (se ? g_hs : g_h + (size_t)z * NTOK * FDIM) + (size_t)m * FDIM + cn;
            *(float4*)(C)     = make_float4(fmaxf(v0.x, 0.f), fmaxf(v0.y, 0.f),
                                            fmaxf(v1.x, 0.f), fmaxf(v1.y, 0.f));
            *(float4*)(C + 4) = make_float4(fmaxf(v2.x, 0.f), fmaxf(v2.y, 0.f),
                                            fmaxf(v3.x, 0.f), fmaxf(v3.y, 0.f));
        } else {
            float w;
            int row;
            if (se) { w = 0.5f; row = m; }
            else {
                int entry = g_lists[z * NTOK + m];
                w = g_gatew[entry];
                row = entry >> 1;
            }
            float* C = out + (size_t)row * DDIM + cn;
            atomicAdd(C + 0, w * v0.x);
            atomicAdd(C + 1, w * v0.y);
            atomicAdd(C + 2, w * v1.x);
            atomicAdd(C + 3, w * v1.y);
            atomicAdd(C + 4, w * v2.x);
            atomicAdd(C + 5, w * v2.y);
            atomicAdd(C + 6, w * v3.x);
            atomicAdd(C + 7, w * v3.y);
        }
    }
}

// ---------------------------------------------------------------------------
extern "C" void kernel_launch(void* const* d_in, const int* in_sizes, int n_in,
                              void* d_out, int out_size) {
    const float* x   = (const float*)d_in[0];
    const float* Wg  = (const float*)d_in[1];
    const float* bg  = (const float*)d_in[2];
    const float* W1  = (const float*)d_in[3];
    const float* b1  = (const float*)d_in[4];
    const float* W2  = (const float*)d_in[5];
    const float* b2  = (const float*)d_in[6];
    const float* Ws1 = (const float*)d_in[7];
    const float* bs1 = (const float*)d_in[8];
    const float* Ws2 = (const float*)d_in[9];
    const float* bs2 = (const float*)d_in[10];
    float* out = (float*)d_out;

    zero_counts_kernel<<<1, 32>>>();
    zero_out_kernel<<<(NTOK * DDIM / 4) / 256, 256>>>(out);
    gate_kernel<<<NTOK / 4, 128>>>(x, Wg, bg);

    // Phase 1: all FFN1 (8 routed + shared). K=512, N=2048.
    mm_kernel<1><<<dim3(FDIM / BN, NTOK / BM, NEXP + 1), 256>>>(
        x, W1, b1, W2, b2, Ws1, bs1, Ws2, bs2, out);
    // Phase 2: all FFN2, atomic accumulate. K=2048, N=512.
    mm_kernel<2><<<dim3(DDIM / BN, NTOK / BM, NEXP + 1), 256>>>(
        x, W1, b1, W2, b2, Ws1, bs1, Ws2, bs2, out);
}